// round 10
// baseline (speedup 1.0000x reference)
#include <cuda_runtime.h>
#include <cuda_bf16.h>
#include <stdint.h>

constexpr int B    = 4;
constexpr int H    = 8;
constexpr int LQ   = 1024;
constexpr int DH   = 64;
constexpr int KLEN = 1024;
constexpr int TBL  = 33;     // 2*MAX_REL_POS + 1
constexpr int TP   = 68;     // padded row stride (272B): bank-skewed
constexpr int PS   = 34;     // S2 row stride

__device__ __forceinline__ void ffma2(unsigned long long& acc,
                                      unsigned long long a,
                                      unsigned long long b)
{
    asm("fma.rn.f32x2 %0, %1, %2, %0;" : "+l"(acc) : "l"(a), "l"(b));
}
__device__ __forceinline__ float f2lo(unsigned long long v) {
    return __uint_as_float((unsigned)v);
}
__device__ __forceinline__ float f2hi(unsigned long long v) {
    return __uint_as_float((unsigned)(v >> 32));
}

// ---------------------------------------------------------------------------
// Fused kernel, one block per (b,q).
// S-compute thread map: h = lane>>2, j = warp*4 + (lane&3)  ->
//   q chunk  = 8 distinct rows x 16B @272B stride -> 1 wavefront
//   t chunk  = 4 distinct rows x 16B               -> 1 wavefront
//   (was 5 wf/chunk in R9; 2.5x less crossbar traffic)
// Gather: warp-uniform idx fast path (sorted time_ids => ~95% of warps have
// one single idx for all 128 k's) -> 1 broadcast LDS per h instead of 4.
// ---------------------------------------------------------------------------
__global__ __launch_bounds__(256)
void relpe_fused(const float* __restrict__ q,
                 const float* __restrict__ table,
                 const int* __restrict__ tids,
                 float* __restrict__ out)
{
    __shared__ __align__(16) float tsh[TBL * TP];   // 8.8 KB
    __shared__ __align__(16) float qsh[H * TP];     // 2.1 KB
    __shared__ float S2[H * PS];                    // 1.1 KB

    const int blk  = blockIdx.x;        // (b,q) index
    const int b    = blk >> 10;
    const int qpos = blk & (LQ - 1);
    const int tid  = threadIdx.x;

    // ---- stage table: 2112 floats = 528 float4 ----
    {
        const float4* t4 = reinterpret_cast<const float4*>(table);
        for (int i = tid; i < (TBL * DH) / 4; i += 256) {
            float4 v = t4[i];
            int j  = i >> 4;          // 16 float4 per row
            int c4 = i & 15;
            *reinterpret_cast<float4*>(&tsh[j * TP + 4 * c4]) = v;
        }
    }
    // ---- stage q slab: 512 floats = 128 float4 ----
    if (tid < (H * DH) / 4) {
        int h  = tid >> 4;
        int c4 = tid & 15;
        float4 v = reinterpret_cast<const float4*>(
            q + (((size_t)b * H + h) * LQ + qpos) * DH)[c4];
        *reinterpret_cast<float4*>(&qsh[h * TP + 4 * c4]) = v;
    }

    // ---- idx for this thread's 4 k values ----
    const int tq = tids[b * KLEN + qpos];
    int4 t4i = reinterpret_cast<const int4*>(tids + (size_t)b * KLEN)[tid];
    int i0 = t4i.x - tq; i0 = i0 < -16 ? -16 : (i0 > 16 ? 16 : i0); i0 += 16;
    int i1 = t4i.y - tq; i1 = i1 < -16 ? -16 : (i1 > 16 ? 16 : i1); i1 += 16;
    int i2 = t4i.z - tq; i2 = i2 < -16 ? -16 : (i2 > 16 ? 16 : i2); i2 += 16;
    int i3 = t4i.w - tq; i3 = i3 < -16 ? -16 : (i3 > 16 ? 16 : i3); i3 += 16;

    // warp-uniform idx detection (idx is h-independent)
    const unsigned FULL = 0xffffffffu;
    const int  ilead = __shfl_sync(FULL, i0, 0);
    const bool uniw  = __all_sync(FULL,
        (i0 == i1) && (i1 == i2) && (i2 == i3) && (i0 == ilead));

    __syncthreads();

    // ---- S compute: h = lane>>2, j = warp*4 + (lane&3) ----
    {
        const int l = tid & 31;
        const int w = tid >> 5;
        const int h = l >> 2;
        const int j = w * 4 + (l & 3);       // 0..31
        const ulonglong2* qrow =
            reinterpret_cast<const ulonglong2*>(&qsh[h * TP]);
        const ulonglong2* trow =
            reinterpret_cast<const ulonglong2*>(&tsh[j * TP]);
        unsigned long long a0 = 0ull, a1 = 0ull;
        #pragma unroll
        for (int c = 0; c < 16; c++) {
            ulonglong2 qa = qrow[c];
            ulonglong2 ta = trow[c];
            ffma2(a0, qa.x, ta.x);
            ffma2(a1, qa.y, ta.y);
        }
        S2[h * PS + j] = (f2lo(a0) + f2hi(a0)) + (f2lo(a1) + f2hi(a1));

        // tail: j = 32, threads 0..7 (h = tid)
        if (tid < H) {
            const ulonglong2* qr2 =
                reinterpret_cast<const ulonglong2*>(&qsh[tid * TP]);
            const ulonglong2* tr2 =
                reinterpret_cast<const ulonglong2*>(&tsh[32 * TP]);
            unsigned long long b0 = 0ull, b1 = 0ull;
            #pragma unroll
            for (int c = 0; c < 16; c++) {
                ulonglong2 qa = qr2[c];
                ulonglong2 ta = tr2[c];
                ffma2(b0, qa.x, ta.x);
                ffma2(b1, qa.y, ta.y);
            }
            S2[tid * PS + 32] = (f2lo(b0) + f2hi(b0)) + (f2lo(b1) + f2hi(b1));
        }
    }
    __syncthreads();

    // ---- gather + stream ----
    if (uniw) {
        // single idx for the whole warp: 1 broadcast LDS per h
        #pragma unroll
        for (int h = 0; h < H; h++) {
            float s = S2[h * PS + ilead];
            float4 v = make_float4(s, s, s, s);
            float4* o4 = reinterpret_cast<float4*>(
                out + ((((size_t)b * H + h) * LQ + qpos) * KLEN));
            __stcs(o4 + tid, v);
        }
    } else {
        #pragma unroll
        for (int h = 0; h < H; h++) {
            const float* row = &S2[h * PS];
            float4 v;
            v.x = row[i0];
            v.y = row[i1];
            v.z = row[i2];
            v.w = row[i3];
            float4* o4 = reinterpret_cast<float4*>(
                out + ((((size_t)b * H + h) * LQ + qpos) * KLEN));
            __stcs(o4 + tid, v);
        }
    }
}

extern "C" void kernel_launch(void* const* d_in, const int* in_sizes, int n_in,
                              void* d_out, int out_size)
{
    const float* q     = (const float*)d_in[0];
    const float* table = (const float*)d_in[1];
    const int*   tids  = (const int*)d_in[2];
    float*       out   = (float*)d_out;

    relpe_fused<<<B * LQ, 256>>>(q, table, tids, out);
}